// round 1
// baseline (speedup 1.0000x reference)
#include <cuda_runtime.h>
#include <math.h>

// Fixed problem shape
#define BB       4
#define SQ       2048
#define SKV      2048
#define DMODEL   1024
#define NHEADS   16
#define HDIM     64

// Scratch (device globals; no allocation allowed)
__device__ float g_Q[BB * NHEADS * SQ * HDIM];     // [B,H,SQ,Dh]
__device__ float g_K[BB * NHEADS * SKV * HDIM];    // [B,H,SKV,Dh]
__device__ float g_V[BB * NHEADS * SKV * HDIM];    // [B,H,SKV,Dh]
__device__ float g_attn[BB * SQ * DMODEL];         // [B*SQ, D]

// ---------------------------------------------------------------------------
// GEMM: Y = X @ W^T + bias.  X:[M,1024] row-major, W:[1024,1024] row-major
// (row n holds W[n, :], contiguous over k).  N = K = 1024.
// LAYOUT 0: Y row-major [M,1024]
// LAYOUT 1: head split  Y[(((m/S)*16 + n/64)*S + m%S)*64 + n%64]
// 128x128 tile, BK=16, 256 threads, 8x8 micro-tile.
// ---------------------------------------------------------------------------
template <int LAYOUT>
__global__ __launch_bounds__(256)
void gemm_bias_kernel(const float* __restrict__ X, const float* __restrict__ W,
                      const float* __restrict__ bias, float* __restrict__ Y,
                      int S)
{
    __shared__ __align__(16) float As[16][132];
    __shared__ __align__(16) float Bs[16][132];

    const int tid = threadIdx.x;
    const int tx  = tid & 15;   // 0..15 -> n micro
    const int ty  = tid >> 4;   // 0..15 -> m micro
    const int m0  = blockIdx.y * 128;
    const int n0  = blockIdx.x * 128;

    float acc[8][8];
#pragma unroll
    for (int i = 0; i < 8; i++)
#pragma unroll
        for (int j = 0; j < 8; j++) acc[i][j] = 0.0f;

    for (int k0 = 0; k0 < 1024; k0 += 16) {
#pragma unroll
        for (int i = 0; i < 2; i++) {
            int v   = tid + (i << 8);
            int row = v >> 2;          // 0..127
            int kq  = (v & 3) << 2;    // 0,4,8,12
            const float4 xv = *reinterpret_cast<const float4*>(
                X + (size_t)(m0 + row) * 1024 + k0 + kq);
            As[kq + 0][row] = xv.x; As[kq + 1][row] = xv.y;
            As[kq + 2][row] = xv.z; As[kq + 3][row] = xv.w;
            const float4 wv = *reinterpret_cast<const float4*>(
                W + (size_t)(n0 + row) * 1024 + k0 + kq);
            Bs[kq + 0][row] = wv.x; Bs[kq + 1][row] = wv.y;
            Bs[kq + 2][row] = wv.z; Bs[kq + 3][row] = wv.w;
        }
        __syncthreads();

#pragma unroll
        for (int k = 0; k < 16; k++) {
            float4 a0 = *reinterpret_cast<const float4*>(&As[k][ty * 8]);
            float4 a1 = *reinterpret_cast<const float4*>(&As[k][ty * 8 + 4]);
            float4 b0 = *reinterpret_cast<const float4*>(&Bs[k][tx * 8]);
            float4 b1 = *reinterpret_cast<const float4*>(&Bs[k][tx * 8 + 4]);
            float a[8] = {a0.x, a0.y, a0.z, a0.w, a1.x, a1.y, a1.z, a1.w};
            float b[8] = {b0.x, b0.y, b0.z, b0.w, b1.x, b1.y, b1.z, b1.w};
#pragma unroll
            for (int i = 0; i < 8; i++)
#pragma unroll
                for (int j = 0; j < 8; j++)
                    acc[i][j] = fmaf(a[i], b[j], acc[i][j]);
        }
        __syncthreads();
    }

    float bb[8];
#pragma unroll
    for (int j = 0; j < 8; j++) bb[j] = bias[n0 + tx * 8 + j];

#pragma unroll
    for (int i = 0; i < 8; i++) {
        int m = m0 + ty * 8 + i;
#pragma unroll
        for (int jj = 0; jj < 2; jj++) {
            int n = n0 + tx * 8 + jj * 4;
            float4 r;
            r.x = acc[i][jj * 4 + 0] + bb[jj * 4 + 0];
            r.y = acc[i][jj * 4 + 1] + bb[jj * 4 + 1];
            r.z = acc[i][jj * 4 + 2] + bb[jj * 4 + 2];
            r.w = acc[i][jj * 4 + 3] + bb[jj * 4 + 3];
            size_t idx;
            if (LAYOUT == 0) {
                idx = (size_t)m * 1024 + n;
            } else {
                int b = m / S;
                int s = m - b * S;
                int h = n >> 6;
                int d = n & 63;
                idx = (((size_t)b * NHEADS + h) * S + s) * 64 + d;
            }
            *reinterpret_cast<float4*>(Y + idx) = r;
        }
    }
}

// ---------------------------------------------------------------------------
// Flash attention: per (b,h), out = softmax(Q K^T / 8) V
// Grid: (SQ/64, B*H). Block: 256 threads.
// BQ=64 q rows per CTA, BKV=32 kv rows per tile, Dh=64.
// Thread (ty=tid/16, tx=tid%16):
//   S micro-tile: rows ty*4..+4, cols tx*2..+2 (64x32)
//   O micro-tile: rows ty*4..+4, dh   tx*4..+4 (64x64)
// Smem: Qs transposed [d][r] (stride 68), KP holds Ks [d][c] (stride 36)
// then reused as Ps [c][r] (stride 68), Vs natural [c][d] (stride 64).
// ---------------------------------------------------------------------------
__global__ __launch_bounds__(256)
void attn_kernel(const float* __restrict__ Q, const float* __restrict__ K,
                 const float* __restrict__ V, float* __restrict__ out)
{
    __shared__ __align__(16) float Qs[64 * 68];   // 17408 B
    __shared__ __align__(16) float KP[64 * 36];   //  9216 B (Ks / Ps union)
    __shared__ __align__(16) float Vs[32 * 64];   //  8192 B

    const int tid = threadIdx.x;
    const int tx  = tid & 15;
    const int ty  = tid >> 4;
    const int ty4 = ty * 4;
    const int tx2 = tx * 2;
    const int tx4 = tx * 4;

    const int bh = blockIdx.y;          // b*16 + h
    const int q0 = blockIdx.x * 64;

    const float* Qp = Q + ((size_t)bh * SQ + q0) * 64;
    const float* Kp = K + (size_t)bh * SKV * 64;
    const float* Vp = V + (size_t)bh * SKV * 64;

    // Load Q tile (64x64) transposed into Qs[d][r]
#pragma unroll
    for (int i = 0; i < 4; i++) {
        int v  = tid + (i << 8);
        int r  = v >> 4;          // 0..63
        int dq = (v & 15) << 2;   // 0..60
        const float4 q4 = *reinterpret_cast<const float4*>(Qp + (size_t)r * 64 + dq);
        Qs[(dq + 0) * 68 + r] = q4.x;
        Qs[(dq + 1) * 68 + r] = q4.y;
        Qs[(dq + 2) * 68 + r] = q4.z;
        Qs[(dq + 3) * 68 + r] = q4.w;
    }

    float m_i[4], l_i[4], o[4][4];
#pragma unroll
    for (int i = 0; i < 4; i++) {
        m_i[i] = -1e30f;
        l_i[i] = 0.0f;
#pragma unroll
        for (int j = 0; j < 4; j++) o[i][j] = 0.0f;
    }
    const float scale = 0.125f;   // 1/sqrt(64)

    for (int t = 0; t < SKV / 32; t++) {
        __syncthreads();   // prior O-gemm done reading KP/Vs; Qs visible after 1st
        const float* Kt = Kp + (size_t)t * 32 * 64;
        const float* Vt = Vp + (size_t)t * 32 * 64;
#pragma unroll
        for (int i = 0; i < 2; i++) {
            int v  = tid + (i << 8);
            int c  = v >> 4;          // 0..31
            int dq = (v & 15) << 2;   // 0..60
            const float4 k4 = *reinterpret_cast<const float4*>(Kt + (size_t)c * 64 + dq);
            KP[(dq + 0) * 36 + c] = k4.x;
            KP[(dq + 1) * 36 + c] = k4.y;
            KP[(dq + 2) * 36 + c] = k4.z;
            KP[(dq + 3) * 36 + c] = k4.w;
            const float4 v4 = *reinterpret_cast<const float4*>(Vt + (size_t)c * 64 + dq);
            *reinterpret_cast<float4*>(&Vs[c * 64 + dq]) = v4;
        }
        __syncthreads();

        // S = Q K^T  (rows ty*4..+4, cols tx*2..+2)
        float s[4][2];
#pragma unroll
        for (int i = 0; i < 4; i++) { s[i][0] = 0.0f; s[i][1] = 0.0f; }
#pragma unroll
        for (int d = 0; d < 64; d++) {
            float4 a  = *reinterpret_cast<const float4*>(&Qs[d * 68 + ty4]);
            float2 bv = *reinterpret_cast<const float2*>(&KP[d * 36 + tx2]);
            float av[4] = {a.x, a.y, a.z, a.w};
#pragma unroll
            for (int i = 0; i < 4; i++) {
                s[i][0] = fmaf(av[i], bv.x, s[i][0]);
                s[i][1] = fmaf(av[i], bv.y, s[i][1]);
            }
        }

        // online softmax (row reductions over 16 tx lanes via shfl_xor)
        float mt[4];
#pragma unroll
        for (int i = 0; i < 4; i++) {
            s[i][0] *= scale; s[i][1] *= scale;
            mt[i] = fmaxf(s[i][0], s[i][1]);
        }
#pragma unroll
        for (int off = 1; off < 16; off <<= 1)
#pragma unroll
            for (int i = 0; i < 4; i++)
                mt[i] = fmaxf(mt[i], __shfl_xor_sync(0xffffffffu, mt[i], off));

        float p[4][2], rs[4], alpha[4];
#pragma unroll
        for (int i = 0; i < 4; i++) {
            float m_new = fmaxf(m_i[i], mt[i]);
            alpha[i] = __expf(m_i[i] - m_new);
            p[i][0] = __expf(s[i][0] - m_new);
            p[i][1] = __expf(s[i][1] - m_new);
            rs[i] = p[i][0] + p[i][1];
            m_i[i] = m_new;
        }
#pragma unroll
        for (int off = 1; off < 16; off <<= 1)
#pragma unroll
            for (int i = 0; i < 4; i++)
                rs[i] += __shfl_xor_sync(0xffffffffu, rs[i], off);
#pragma unroll
        for (int i = 0; i < 4; i++) {
            l_i[i] = l_i[i] * alpha[i] + rs[i];
#pragma unroll
            for (int j = 0; j < 4; j++) o[i][j] *= alpha[i];
        }

        __syncthreads();   // all threads done reading Ks from KP

        // write P transposed: Ps[c][r], stride 68
#pragma unroll
        for (int j = 0; j < 2; j++) {
            float4 pv = make_float4(p[0][j], p[1][j], p[2][j], p[3][j]);
            *reinterpret_cast<float4*>(&KP[(tx2 + j) * 68 + ty4]) = pv;
        }
        __syncthreads();

        // O += P V  (rows ty*4..+4, dh tx*4..+4)
#pragma unroll
        for (int c = 0; c < 32; c++) {
            float4 a  = *reinterpret_cast<const float4*>(&KP[c * 68 + ty4]);
            float4 bv = *reinterpret_cast<const float4*>(&Vs[c * 64 + tx4]);
            float av[4] = {a.x, a.y, a.z, a.w};
            float bb[4] = {bv.x, bv.y, bv.z, bv.w};
#pragma unroll
            for (int i = 0; i < 4; i++)
#pragma unroll
                for (int j = 0; j < 4; j++)
                    o[i][j] = fmaf(av[i], bb[j], o[i][j]);
        }
    }

    // epilogue: normalize and write to attn buffer [B*SQ, 1024]
    const int b = bh >> 4;
    const int h = bh & 15;
    const size_t row_base = (size_t)b * SQ + q0 + ty4;
#pragma unroll
    for (int i = 0; i < 4; i++) {
        float inv = 1.0f / l_i[i];
        float4 r = make_float4(o[i][0] * inv, o[i][1] * inv,
                               o[i][2] * inv, o[i][3] * inv);
        *reinterpret_cast<float4*>(out + (row_base + i) * 1024 + h * 64 + tx4) = r;
    }
}

// ---------------------------------------------------------------------------
extern "C" void kernel_launch(void* const* d_in, const int* in_sizes, int n_in,
                              void* d_out, int out_size)
{
    (void)in_sizes; (void)n_in; (void)out_size;
    const float* query = (const float*)d_in[0];
    const float* keyval = (const float*)d_in[1];
    const float* Wq = (const float*)d_in[2];
    const float* bq = (const float*)d_in[3];
    const float* Wk = (const float*)d_in[4];
    const float* bk = (const float*)d_in[5];
    const float* Wv = (const float*)d_in[6];
    const float* bv = (const float*)d_in[7];
    const float* Wo = (const float*)d_in[8];
    const float* bo = (const float*)d_in[9];
    float* out = (float*)d_out;

    float *qbuf, *kbuf, *vbuf, *abuf;
    cudaGetSymbolAddress((void**)&qbuf, g_Q);
    cudaGetSymbolAddress((void**)&kbuf, g_K);
    cudaGetSymbolAddress((void**)&vbuf, g_V);
    cudaGetSymbolAddress((void**)&abuf, g_attn);

    dim3 blk(256);
    dim3 grid_proj(8, (BB * SQ) / 128);   // (8, 64)

    gemm_bias_kernel<1><<<grid_proj, blk>>>(query,  Wq, bq, qbuf, SQ);
    gemm_bias_kernel<1><<<grid_proj, blk>>>(keyval, Wk, bk, kbuf, SKV);
    gemm_bias_kernel<1><<<grid_proj, blk>>>(keyval, Wv, bv, vbuf, SKV);

    dim3 grid_attn(SQ / 64, BB * NHEADS); // (32, 64)
    attn_kernel<<<grid_attn, blk>>>(qbuf, kbuf, vbuf, abuf);

    gemm_bias_kernel<0><<<grid_proj, blk>>>(abuf, Wo, bo, out, SQ);
}